// round 14
// baseline (speedup 1.0000x reference)
#include <cuda_runtime.h>
#include <cuda_bf16.h>

// Sampler_51419348468365 — FINAL
//
// Value-level reduction: reference ends with
//   out = stop_gradient(1 - y) + y
// stop_gradient is identity on values => out == (1 - y) + y == 1.0f to
// <= ~1.2e-7 fp32 rounding (y = segment-softmax in (0,1)); tolerance 1e-3.
// Entire gather/Gumbel/segment-softmax pipeline is value-dead; kernel is a
// constant 1.0f fill of out_size floats (4 MB).
//
// Rounds 1-13 established the e2e floor (6.40-6.66 us) is graph-replay +
// launch overhead, invariant to node content (even a memset-node graph with
// no kernel measures the same). This is the terminal form: zero-predicate
// exact-fit kernel for out_size % 1024 == 0 (the actual shape) — one
// unconditional STG.E.128 per thread, ~4 SASS instructions total; generic
// bounds-checked fallback for any other shape.

__global__ __launch_bounds__(256, 1)
void Sampler_fill_ones_exact(float4* __restrict__ out4) {
    out4[blockIdx.x * 256 + threadIdx.x] =
        make_float4(1.0f, 1.0f, 1.0f, 1.0f);
}

__global__ __launch_bounds__(256, 1)
void Sampler_fill_ones_generic(float* __restrict__ out, int n_total) {
    int i = blockIdx.x * 256 + threadIdx.x;
    if (i < n_total) out[i] = 1.0f;
}

extern "C" void kernel_launch(void* const* d_in, const int* in_sizes, int n_in,
                              void* d_out, int out_size) {
    (void)d_in; (void)in_sizes; (void)n_in;
    if (out_size >= 1024 && (out_size & 1023) == 0) {
        // Actual shape: 2^20 floats -> 1024 CTAs x 256 threads x 1 float4.
        Sampler_fill_ones_exact<<<out_size / 1024, 256>>>((float4*)d_out);
    } else {
        int n = out_size < 1 ? 1 : out_size;
        Sampler_fill_ones_generic<<<(n + 255) / 256, 256>>>((float*)d_out,
                                                            out_size);
    }
}

// round 15
// speedup vs baseline: 1.0437x; 1.0437x over previous
#include <cuda_runtime.h>
#include <cuda_bf16.h>

// Sampler_51419348468365 — FINAL (R2 configuration; best observed e2e 6.400 us)
//
// Value-level reduction: the reference ends with
//   out = stop_gradient(1 - y) + y
// stop_gradient is identity on values => out == (1 - y) + y == 1.0f to
// within <= ~1.2e-7 fp32 rounding (y = segment-softmax output in (0,1));
// bench tolerance is 1e-3. The entire gather -> Gumbel -> segment-softmax
// -> gather pipeline is value-dead; zero input bytes are read. Optimal
// kernel = constant 1.0f fill of out_size floats (4 MB, ~0.35 us of
// L2-resident store traffic at the 6300 B/cyc LTS cap).
//
// Convergence evidence (rounds 1-14, 8 benched submissions):
//  - six structurally distinct fills (fat grid-stride, thin STG @256/@512
//    threads/block, single-wave MLP=8, driver cuMemsetD32Async memset node,
//    zero-predicate exact-fit): e2e 6.40-6.88 us, uncorrelated with content.
//  - identical binary re-measured 4x: 6.400/6.656/6.656/6.624 us.
//  - kernel-free memset-node graph: 6.624 us => floor is graph-replay +
//    launch + sync overhead, invariant to the .cu.
//  - identical SASS spans 3.90-4.32 us in ncu (DVFS/ramp noise).
// Conclusion: measurement floor reached; this is the best-measured form.
//
// Form: one predicated STG.E.128 per thread, 1024 CTAs x 256 threads; tail
// (out_size % 4) covered by trailing threads (dead code for out_size = 2^20).

__global__ __launch_bounds__(256, 1)
void Sampler_fill_ones(float4* __restrict__ out4, int n4,
                       float* __restrict__ out_tail, int n_total) {
    int i = blockIdx.x * 256 + threadIdx.x;
    const float4 ones = make_float4(1.0f, 1.0f, 1.0f, 1.0f);
    if (i < n4) {
        out4[i] = ones;
    }
    int t = i - n4;  // >= 0 only for trailing threads
    if (t >= 0 && 4 * n4 + t < n_total) {
        out_tail[4 * n4 + t] = 1.0f;
    }
}

extern "C" void kernel_launch(void* const* d_in, const int* in_sizes, int n_in,
                              void* d_out, int out_size) {
    (void)d_in; (void)in_sizes; (void)n_in;
    float* out = (float*)d_out;
    int n4 = out_size / 4;                         // 262144
    int total_threads = n4 + (out_size - 4 * n4);  // + tail threads
    if (total_threads < 1) total_threads = 1;
    int blocks = (total_threads + 255) / 256;      // 1024 blocks for 2^20
    Sampler_fill_ones<<<blocks, 256>>>((float4*)out, n4, out, out_size);
}